// round 14
// baseline (speedup 1.0000x reference)
#include <cuda_runtime.h>
#include <cstdint>

#define THREADS 256
#define HCAP 768            // per-row fast-path candidate buffer (2 rows per CTA)
#define FCAP (2 * HCAP)     // fallback buffer = union of both halves (k <= 1536)

// Monotone float<->uint key mapping (total order matching IEEE float order)
__device__ __forceinline__ unsigned f2key(float f) {
    unsigned u = __float_as_uint(f);
    return (u & 0x80000000u) ? ~u : (u | 0x80000000u);
}
__device__ __forceinline__ float key2f(unsigned kk) {
    unsigned u = (kk & 0x80000000u) ? (kk ^ 0x80000000u) : ~kk;
    return __uint_as_float(u);
}

// Rare-path append of one float4's hits (as integer keys): one shared atomic per pack.
__device__ __forceinline__ void append_pack(float4 v, float t0, unsigned* buf,
                                            int* cnt, int cap) {
    int h = (v.x > t0) + (v.y > t0) + (v.z > t0) + (v.w > t0);
    int base = atomicAdd(cnt, h);
    int p = base;
    if (v.x > t0) { if (p < cap) buf[p] = f2key(v.x); p++; }
    if (v.y > t0) { if (p < cap) buf[p] = f2key(v.y); p++; }
    if (v.z > t0) { if (p < cap) buf[p] = f2key(v.z); p++; }
    if (v.w > t0) { if (p < cap) buf[p] = f2key(v.w); p++; }
}

// Streaming filter over one row: append keys of elements > t0 into buf.
__device__ __forceinline__ void stream_row(const float* __restrict__ xr, int row_len,
                                           float t0, unsigned* buf, int* cnt, int cap,
                                           int tid) {
    const int nv4 = row_len >> 2;
    const float4* __restrict__ x4 = (const float4*)xr;
    int i = tid;
    for (; i + 3 * THREADS < nv4; i += 4 * THREADS) {
        float4 a = __ldg(&x4[i]);
        float4 b = __ldg(&x4[i + THREADS]);
        float4 c4 = __ldg(&x4[i + 2 * THREADS]);
        float4 d = __ldg(&x4[i + 3 * THREADS]);
        float ma = fmaxf(fmaxf(a.x, a.y), fmaxf(a.z, a.w));
        float mb = fmaxf(fmaxf(b.x, b.y), fmaxf(b.z, b.w));
        float mc = fmaxf(fmaxf(c4.x, c4.y), fmaxf(c4.z, c4.w));
        float md = fmaxf(fmaxf(d.x, d.y), fmaxf(d.z, d.w));
        if (ma > t0) append_pack(a, t0, buf, cnt, cap);
        if (mb > t0) append_pack(b, t0, buf, cnt, cap);
        if (mc > t0) append_pack(c4, t0, buf, cnt, cap);
        if (md > t0) append_pack(d, t0, buf, cnt, cap);
    }
    for (; i < nv4; i += THREADS) {
        float4 a = __ldg(&x4[i]);
        float ma = fmaxf(fmaxf(a.x, a.y), fmaxf(a.z, a.w));
        if (ma > t0) append_pack(a, t0, buf, cnt, cap);
    }
    for (int j = (nv4 << 2) + tid; j < row_len; j += THREADS) {
        float f = __ldg(&xr[j]);
        if (f > t0) { int s = atomicAdd(cnt, 1); if (s < cap) buf[s] = f2key(f); }
    }
}

// Exact stable ranking of M keys (no padding needed); writes ranks < k.
// rank_i = #{j<i : kj >= ki} + #{j>i : kj > ki}. Equal keys are interchangeable
// floats => output deterministic regardless of insertion order. key 16B-aligned.
__device__ __forceinline__ void rank_nopads(const unsigned* __restrict__ key, int M,
                                            int k, float* __restrict__ outr,
                                            int t, int nt) {
    const int nb = M >> 2;                 // full uint4 blocks
    const uint4* __restrict__ k4 = (const uint4*)key;
    for (int i = t; i < M; i += nt) {
        const unsigned ki = key[i];
        const int ib = i >> 2;
        int rank = 0;
        const int bhi = (ib < nb) ? ib : nb;
        #pragma unroll 4
        for (int b = 0; b < bhi; b++) {    // j < i region: >=
            uint4 v = k4[b];
            rank += (v.x >= ki) + (v.y >= ki) + (v.z >= ki) + (v.w >= ki);
        }
        if (ib < nb) {                     // straddling block
            uint4 v = k4[ib];
            int m = i & 3;
            rank += (0 < m) ? (v.x >= ki) : (v.x > ki);
            rank += (1 < m) ? (v.y >= ki) : (v.y > ki);
            rank += (2 < m) ? (v.z >= ki) : (v.z > ki);
            rank += (3 < m) ? (v.w >= ki) : (v.w > ki);
        }
        #pragma unroll 4
        for (int b = ib + 1; b < nb; b++) { // j > i region: >
            uint4 v = k4[b];
            rank += (v.x > ki) + (v.y > ki) + (v.z > ki) + (v.w > ki);
        }
        for (int j = nb << 2; j < M; j++) { // scalar tail (<=3 elems)
            unsigned kj = key[j];
            rank += (j < i) ? (kj >= ki) : (kj > ki);
        }
        if (rank < k) outr[rank] = key2f(ki);
    }
}

__global__ void __launch_bounds__(THREADS)
TopKPooling_20796231647786_kernel(
    const float* __restrict__ x, const int* __restrict__ kp,
    float* __restrict__ out, long long n_x, long long out_n)
{
    __shared__ __align__(16) unsigned s_key[FCAP];
    __shared__ int s_cnt[2];
    __shared__ int s_c2;

    const int k = *kp;
    const long long rows = out_n / k;
    const int row_len = (int)(n_x / rows);
    const long long npairs = (rows + 1) >> 1;
    const int tid = threadIdx.x;
    const int lane = tid & 31;

    for (long long pr = blockIdx.x; pr < npairs; pr += gridDim.x) {
        const long long r0 = pr << 1;
        const int nrow = (r0 + 1 < rows) ? 2 : 1;

        if (tid < 2) s_cnt[tid] = 0;
        __syncthreads();

        // ---- Stream both rows back-to-back (independent buffers/counters) ----
        for (int h = 0; h < nrow; h++)
            stream_row(x + (r0 + h) * (long long)row_len, row_len, 2.55f,
                       s_key + h * HCAP, &s_cnt[h], HCAP, tid);
        __syncthreads();

        // ---- Fast epilogue: warps 0-3 rank row0, warps 4-7 rank row1 ----
        {
            int half = tid >> 7;          // 0 or 1
            int t128 = tid & 127;
            if (half < nrow) {
                int c = s_cnt[half];
                if (c >= k && c <= HCAP)
                    rank_nopads(s_key + half * HCAP, c, k,
                                out + (r0 + half) * (long long)k, t128, 128);
            }
        }

        // ---- Rare slow path per row (uniform branch on post-barrier smem) ----
        for (int h = 0; h < nrow; h++) {
            int c = s_cnt[h];
            if (c < k || c > HCAP) {
                __syncthreads();          // fence: fast rankers done before buffer reuse
                const float* __restrict__ xr = x + (r0 + h) * (long long)row_len;
                float* __restrict__ outr = out + (r0 + h) * (long long)k;
                // retry with loose threshold over the full buffer
                if (tid == 0) s_c2 = 0;
                __syncthreads();
                stream_row(xr, row_len, 2.00f, s_key, &s_c2, FCAP, tid);
                __syncthreads();
                int c2 = s_c2;
                if (c2 >= k && c2 <= FCAP) {
                    rank_nopads(s_key, c2, k, outr, tid, THREADS);
                } else {
                    // exact bisection for the k-th largest key (any input, k <= FCAP)
                    long long lo = -1, hi = 0xFFFFFFFFll;
                    while (lo + 1 < hi) {
                        long long mid = (lo + hi) >> 1;
                        unsigned tkey = (unsigned)mid;
                        if (tid == 0) s_c2 = 0;
                        __syncthreads();
                        int local = 0;
                        for (int j = tid; j < row_len; j += THREADS)
                            local += (f2key(__ldg(&xr[j])) > tkey) ? 1 : 0;
                        #pragma unroll
                        for (int o = 16; o; o >>= 1)
                            local += __shfl_down_sync(0xFFFFFFFFu, local, o);
                        if (lane == 0) atomicAdd(&s_c2, local);
                        __syncthreads();
                        int cc = s_c2;
                        if (cc < k) hi = mid; else lo = mid;
                        __syncthreads();
                    }
                    unsigned K = (unsigned)hi;          // K = k-th largest key
                    if (tid == 0) s_c2 = 0;
                    __syncthreads();
                    for (int j = tid; j < row_len; j += THREADS) {
                        unsigned kf = f2key(__ldg(&xr[j]));
                        if (kf > K) { int s = atomicAdd(&s_c2, 1); if (s < FCAP) s_key[s] = kf; }
                    }
                    __syncthreads();
                    int M = s_c2;                       // M < k <= FCAP
                    rank_nopads(s_key, M, k, outr, tid, THREADS);
                    float fk = key2f(K);                // fill duplicates of k-th value
                    for (int j = M + tid; j < k; j += THREADS) outr[j] = fk;
                }
                __syncthreads();          // buffer stable before next slow row / exit
            }
        }

        // protect s_cnt/s_key reuse only if another pair follows
        if (pr + gridDim.x < npairs) __syncthreads();
    }
}

extern "C" void kernel_launch(void* const* d_in, const int* in_sizes, int n_in,
                              void* d_out, int out_size) {
    const float* x = (const float*)d_in[0];
    const int* kp = (const int*)d_in[1];
    long long n_x = (long long)in_sizes[0];
    long long out_n = (long long)out_size;
    long long rows_guess = (out_n + 63) / 64;     // exact when k==64; loop covers rest
    int grid = (int)((rows_guess + 1) / 2);
    if (grid < 1) grid = 1;
    TopKPooling_20796231647786_kernel<<<grid, THREADS>>>(x, kp, (float*)d_out, n_x, out_n);
}